// round 15
// baseline (speedup 1.0000x reference)
#include <cuda_runtime.h>
#include <cuda_fp16.h>
#include <math.h>
#include <stdint.h>

#define NROWS 4096
#define DIM   512
#define MARGIN 0.3f
#define FLT_BIG 3.402823466e+38f

#define BM 128
#define BN 128
#define BKH 64          // k per chunk, in halves (128 bytes per row)
#define SSTH 72         // smem row stride in halves (144 B); stride = 4 banks mod 32
#define SSTW (SSTH / 2) // 36 words
#define NCH (DIM / BKH) // 8 k-chunks
#define NTILE (NROWS / BM)              // 32
#define NTRI  (NTILE * (NTILE + 1) / 2) // 528 upper-triangular tiles
#define NFB 16          // finalize blocks
#define SMEM_BYTES (2 * 2 * BM * SSTH * 2)   // 2 ops x 2 stages x 128 x 144B = 73728

// Scratch (device globals: no allocation allowed)
__device__ __half   g_e[NROWS * DIM];   // normalized fp16 embeddings
__device__ unsigned g_ap_bits[NROWS];   // min-gram-over-positives (monotone key)
__device__ unsigned g_an_bits[NROWS];   // max-gram-over-negatives (monotone key)
__device__ float    g_psum[NFB];
__device__ int      g_pcnt[NFB];
__device__ int      g_ticket;           // zero-init; last finalize block resets

#define AP_IDENT 0xFFFFFFFFu   // identity for key-min (only NaN maps here)
#define AN_IDENT 0u            // identity for key-max (only NaN maps here)

// monotone float <-> uint key (order-preserving for all finite floats)
__device__ __forceinline__ unsigned fkey(float x) {
    unsigned b = __float_as_uint(x);
    return (b & 0x80000000u) ? ~b : (b | 0x80000000u);
}
__device__ __forceinline__ float funkey(unsigned k) {
    unsigned b = (k & 0x80000000u) ? (k ^ 0x80000000u) : ~k;
    return __uint_as_float(b);
}

__device__ __forceinline__ uint32_t h2_as_u32(__half2 h) {
    return *reinterpret_cast<uint32_t*>(&h);
}

// ---------------------------------------------------------------------------
// normalize -> fp16 + per-row reduction-buffer reset.
// TWO rows per warp (independent chains -> 8 loads in flight, 2x latency
// hiding). Per-row summation order identical to the verified version, so
// g_e is bitwise unchanged.
// ---------------------------------------------------------------------------
__global__ void normalize_kernel(const float* __restrict__ emb) {
    const int w = threadIdx.x >> 5;        // 0..7
    const int lane = threadIdx.x & 31;
    const int row0 = (blockIdx.x * 8 + w) * 2;
    const int row1 = row0 + 1;
    if (lane == 0) {
        g_ap_bits[row0] = AP_IDENT;  g_an_bits[row0] = AN_IDENT;
        g_ap_bits[row1] = AP_IDENT;  g_an_bits[row1] = AN_IDENT;
    }
    const float4* in0 = (const float4*)(emb + (size_t)row0 * DIM);
    const float4* in1 = (const float4*)(emb + (size_t)row1 * DIM);
    float4 v0[4], v1[4];
    #pragma unroll
    for (int i = 0; i < 4; i++) { v0[i] = in0[lane + 32 * i]; }
    #pragma unroll
    for (int i = 0; i < 4; i++) { v1[i] = in1[lane + 32 * i]; }
    float ss0 = 0.0f, ss1 = 0.0f;
    #pragma unroll
    for (int i = 0; i < 4; i++) {
        ss0 += v0[i].x * v0[i].x + v0[i].y * v0[i].y + v0[i].z * v0[i].z + v0[i].w * v0[i].w;
        ss1 += v1[i].x * v1[i].x + v1[i].y * v1[i].y + v1[i].z * v1[i].z + v1[i].w * v1[i].w;
    }
    #pragma unroll
    for (int o = 16; o > 0; o >>= 1) {
        ss0 += __shfl_xor_sync(0xffffffffu, ss0, o);
        ss1 += __shfl_xor_sync(0xffffffffu, ss1, o);
    }
    const float inv0 = 1.0f / fmaxf(sqrtf(ss0), 1e-12f);
    const float inv1 = 1.0f / fmaxf(sqrtf(ss1), 1e-12f);
    uint2* out0 = (uint2*)(g_e + (size_t)row0 * DIM);
    uint2* out1 = (uint2*)(g_e + (size_t)row1 * DIM);
    #pragma unroll
    for (int i = 0; i < 4; i++) {
        uint2 p0, p1;
        p0.x = h2_as_u32(__floats2half2_rn(v0[i].x * inv0, v0[i].y * inv0));
        p0.y = h2_as_u32(__floats2half2_rn(v0[i].z * inv0, v0[i].w * inv0));
        p1.x = h2_as_u32(__floats2half2_rn(v1[i].x * inv1, v1[i].y * inv1));
        p1.y = h2_as_u32(__floats2half2_rn(v1[i].z * inv1, v1[i].w * inv1));
        out0[lane + 32 * i] = p0;
        out1[lane + 32 * i] = p1;
    }
}

// ---------------------------------------------------------------------------
// Tensor-core gram (fp16 m16n8k16, f32 accum), upper-triangular tiles,
// BK=64 halves + 2-stage cp.async (1 barrier/chunk), ldmatrix frag loads,
// gram-space dual-axis epilogue.  [UNCHANGED from the verified 43.5us run]
// ---------------------------------------------------------------------------
#define MMA_F16(cc, aa, bb)                                                    \
    asm volatile(                                                              \
        "mma.sync.aligned.m16n8k16.row.col.f32.f16.f16.f32 "                   \
        "{%0,%1,%2,%3}, {%4,%5,%6,%7}, {%8,%9}, {%0,%1,%2,%3};"                \
        : "+f"((cc)[0]), "+f"((cc)[1]), "+f"((cc)[2]), "+f"((cc)[3])           \
        : "r"((aa)[0]), "r"((aa)[1]), "r"((aa)[2]), "r"((aa)[3]),              \
          "r"((bb)[0]), "r"((bb)[1]))

#define LDSM4(r0, r1, r2, r3, addr)                                            \
    asm volatile("ldmatrix.sync.aligned.m8n8.x4.shared.b16 {%0,%1,%2,%3}, [%4];" \
                 : "=r"(r0), "=r"(r1), "=r"(r2), "=r"(r3) : "r"(addr))

#define CP16(dst, src)                                                         \
    asm volatile("cp.async.cg.shared.global [%0], [%1], 16;"                   \
                 :: "r"(dst), "l"(src))
#define CP_COMMIT() asm volatile("cp.async.commit_group;")
#define CP_WAIT0()  asm volatile("cp.async.wait_group 0;")

__device__ __forceinline__ int tri_offset(int bi) {
    return bi * NTILE - bi * (bi - 1) / 2;
}

extern __shared__ __half dynsmem[];

__global__ __launch_bounds__(256, 2)
void gram_tc_kernel(const int* __restrict__ labels) {
    __shared__ int sli[BM];
    __shared__ int slj[BN];

    // decode linear tile id -> (bi, bj), bi <= bj
    const int u = blockIdx.x;
    int bi = (int)((65.0f - sqrtf(65.0f * 65.0f - 8.0f * (float)u)) * 0.5f);
    while (tri_offset(bi) > u) bi--;
    while (tri_offset(bi + 1) <= u) bi++;
    const int bj = bi + (u - tri_offset(bi));

    const int tid = threadIdx.x;
    const int i0 = bi * BM;
    const int j0 = bj * BN;
    const bool offdiag = (bi != bj);

    if (tid < 128) sli[tid] = labels[i0 + tid];
    else           slj[tid - 128] = labels[j0 + (tid - 128)];

    const int warp = tid >> 5;
    const int lane = tid & 31;
    const int wm = warp >> 2;      // 0..1 -> 64-row band
    const int wn = warp & 3;       // 0..3 -> 32-col band
    const int g  = lane >> 2;      // 0..7
    const int t  = lane & 3;       // 0..3

    // staging map: thread covers rows {r, r+32, r+64, r+96}, 16B (8 halves)
    const int r  = tid >> 3;       // 0..31
    const int c8 = (tid & 7) * 8;  // 0,8,...,56 (halves)
    const __half* gA = g_e + (size_t)(i0 + r) * DIM + c8;
    const __half* gB = g_e + (size_t)(j0 + r) * DIM + c8;

    // dynamic smem layout: [A stage0][A stage1][B stage0][B stage1]
    __half* Abase = dynsmem;
    __half* Bbase = dynsmem + 2 * BM * SSTH;
    const uint32_t smA = (uint32_t)__cvta_generic_to_shared(Abase);
    const uint32_t smB = (uint32_t)__cvta_generic_to_shared(Bbase);
    const uint32_t sA0 = smA + (uint32_t)(r * SSTH + c8) * 2u;
    const uint32_t sB0 = smB + (uint32_t)(r * SSTH + c8) * 2u;
    const uint32_t STAGE = (uint32_t)(BM * SSTH) * 2u;   // bytes per stage
    const uint32_t ROW32 = (uint32_t)(32 * SSTH) * 2u;   // +32 rows, bytes
    const size_t   G32   = (size_t)32 * DIM;             // +32 rows, halves

    // ldmatrix per-lane base addresses (bytes)
    const int tsel = lane >> 3;
    const int l8 = lane & 7;
    const uint32_t aAddr0 = smA +
        (uint32_t)(((wm * 64 + ((tsel & 1) << 3) + l8) * SSTW + ((tsel >> 1) << 2)) * 4);
    const uint32_t bAddr0 = smB +
        (uint32_t)(((wn * 32 + ((tsel >> 1) << 3) + l8) * SSTW + ((tsel & 1) << 2)) * 4);
    const uint32_t MT16 = (uint32_t)(16 * SSTW * 4);   // +16 rows, bytes

    float c[4][4][4];
    #pragma unroll
    for (int mt = 0; mt < 4; mt++)
        #pragma unroll
        for (int nt = 0; nt < 4; nt++)
            #pragma unroll
            for (int e = 0; e < 4; e++) c[mt][nt][e] = 0.0f;

    // prologue: prefetch chunk 0 into stage 0
    #pragma unroll
    for (int h = 0; h < 4; h++) {
        CP16(sA0 + h * ROW32, gA + h * G32);
        CP16(sB0 + h * ROW32, gB + h * G32);
    }
    CP_COMMIT();

    for (int ch = 0; ch < NCH; ch++) {
        const int s = ch & 1;
        CP_WAIT0();
        __syncthreads();   // stage-ch data visible + compute(ch-1) done everywhere

        if (ch + 1 < NCH) {
            const uint32_t so = ((ch + 1) & 1) ? STAGE : 0u;
            const int kc = (ch + 1) * BKH;
            #pragma unroll
            for (int h = 0; h < 4; h++) {
                CP16(sA0 + so + h * ROW32, gA + h * G32 + kc);
                CP16(sB0 + so + h * ROW32, gB + h * G32 + kc);
            }
            CP_COMMIT();
        }

        const uint32_t stA = aAddr0 + s * STAGE;
        const uint32_t stB = bAddr0 + s * STAGE;
        #pragma unroll
        for (int ks = 0; ks < 4; ks++) {        // 4 x k16 per 64-half chunk
            const uint32_t kOff = ks * 32;      // 8 words = 32 bytes
            uint32_t a[4][4], b[4][2];
            #pragma unroll
            for (int mt = 0; mt < 4; mt++)
                LDSM4(a[mt][0], a[mt][1], a[mt][2], a[mt][3],
                      stA + mt * MT16 + kOff);
            #pragma unroll
            for (int p = 0; p < 2; p++)
                LDSM4(b[2 * p][0], b[2 * p][1], b[2 * p + 1][0], b[2 * p + 1][1],
                      stB + p * MT16 + kOff);
            #pragma unroll
            for (int mt = 0; mt < 4; mt++)
                #pragma unroll
                for (int nt = 0; nt < 4; nt++)
                    MMA_F16(c[mt][nt], a[mt], b[nt]);
        }
    }

    // -------- epilogue (gram space: pos -> min gram, neg -> max gram) --------
    #pragma unroll
    for (int mt = 0; mt < 4; mt++) {
        const int lr0 = wm * 64 + mt * 16 + g;
        const int lr1 = lr0 + 8;
        const int ig0 = i0 + lr0, ig1 = i0 + lr1;
        const int li0 = sli[lr0], li1 = sli[lr1];
        float gp0 = FLT_BIG, gn0 = -FLT_BIG;
        float gp1 = FLT_BIG, gn1 = -FLT_BIG;
        #pragma unroll
        for (int nt = 0; nt < 4; nt++) {
            #pragma unroll
            for (int e = 0; e < 2; e++) {
                const int ljl = wn * 32 + nt * 8 + 2 * t + e;
                const int jg = j0 + ljl;
                const int lj = slj[ljl];
                float v0 = c[mt][nt][e];
                float v1 = c[mt][nt][2 + e];
                if (li0 == lj) { if (ig0 != jg) gp0 = fminf(gp0, v0); }
                else           gn0 = fmaxf(gn0, v0);
                if (li1 == lj) { if (ig1 != jg) gp1 = fminf(gp1, v1); }
                else           gn1 = fmaxf(gn1, v1);
            }
        }
        #pragma unroll
        for (int off = 1; off < 4; off <<= 1) {
            gp0 = fminf(gp0, __shfl_xor_sync(0xffffffffu, gp0, off, 4));
            gn0 = fmaxf(gn0, __shfl_xor_sync(0xffffffffu, gn0, off, 4));
            gp1 = fminf(gp1, __shfl_xor_sync(0xffffffffu, gp1, off, 4));
            gn1 = fmaxf(gn1, __shfl_xor_sync(0xffffffffu, gn1, off, 4));
        }
        if (t == 0) {
            if (gp0 <  FLT_BIG) atomicMin(&g_ap_bits[ig0], fkey(gp0));
            if (gn0 > -FLT_BIG) atomicMax(&g_an_bits[ig0], fkey(gn0));
            if (gp1 <  FLT_BIG) atomicMin(&g_ap_bits[ig1], fkey(gp1));
            if (gn1 > -FLT_BIG) atomicMax(&g_an_bits[ig1], fkey(gn1));
        }
    }

    // Column pass via symmetry (off-diagonal tiles; i/j ranges disjoint)
    if (offdiag) {
        #pragma unroll
        for (int nt = 0; nt < 4; nt++) {
            #pragma unroll
            for (int e = 0; e < 2; e++) {
                const int ljl = wn * 32 + nt * 8 + 2 * t + e;
                const int lj = slj[ljl];
                float gp = FLT_BIG, gn = -FLT_BIG;
                #pragma unroll
                for (int mt = 0; mt < 4; mt++) {
                    const int lr0 = wm * 64 + mt * 16 + g;
                    const int li0 = sli[lr0], li1 = sli[lr0 + 8];
                    float v0 = c[mt][nt][e];
                    float v1 = c[mt][nt][2 + e];
                    if (li0 == lj) gp = fminf(gp, v0); else gn = fmaxf(gn, v0);
                    if (li1 == lj) gp = fminf(gp, v1); else gn = fmaxf(gn, v1);
                }
                #pragma unroll
                for (int off = 4; off < 32; off <<= 1) {
                    gp = fminf(gp, __shfl_xor_sync(0xffffffffu, gp, off, 32));
                    gn = fmaxf(gn, __shfl_xor_sync(0xffffffffu, gn, off, 32));
                }
                if (lane < 4) {   // g == 0 lanes hold the result
                    const int jg = j0 + ljl;
                    if (gp <  FLT_BIG) atomicMin(&g_ap_bits[jg], fkey(gp));
                    if (gn > -FLT_BIG) atomicMax(&g_an_bits[jg], fkey(gn));
                }
            }
        }
    }
}

// ---------------------------------------------------------------------------
// finalize: 16 blocks, 1 row/thread. Validity = both reduction keys changed
// from identity. Last block (ticket) sums the 16 fixed partials.
// ---------------------------------------------------------------------------
__global__ void finalize_kernel(float* __restrict__ out) {
    const int tid = threadIdx.x;
    const int i = blockIdx.x * 256 + tid;
    unsigned apk = g_ap_bits[i];
    unsigned ank = g_an_bits[i];
    float loss = 0.0f;
    int valid = 0;
    if (apk != AP_IDENT && ank != AN_IDENT) {
        float gmin = funkey(apk);   // min gram over positives
        float gmax = funkey(ank);   // max gram over negatives
        float ap = sqrtf(fmaxf(2.0f - 2.0f * gmin, 0.0f));
        float an = sqrtf(fmaxf(2.0f - 2.0f * gmax, 0.0f));
        loss = fmaxf(ap - an + MARGIN, 0.0f);
        valid = 1;
    }
    __shared__ float ssum[256];
    __shared__ int   scnt[256];
    ssum[tid] = loss; scnt[tid] = valid;
    __syncthreads();
    for (int s = 128; s > 0; s >>= 1) {
        if (tid < s) { ssum[tid] += ssum[tid + s]; scnt[tid] += scnt[tid + s]; }
        __syncthreads();
    }
    __shared__ bool last;
    if (tid == 0) {
        g_psum[blockIdx.x] = ssum[0];
        g_pcnt[blockIdx.x] = scnt[0];
        __threadfence();
        last = (atomicAdd(&g_ticket, 1) == NFB - 1);
    }
    __syncthreads();
    if (last && tid == 0) {
        float s = 0.0f;
        int c = 0;
        #pragma unroll
        for (int b = 0; b < NFB; b++) { s += g_psum[b]; c += g_pcnt[b]; }
        out[0] = (c > 0) ? (s / (float)c) : 0.0f;
        g_ticket = 0;   // reset for next graph replay
    }
}

// ---------------------------------------------------------------------------
extern "C" void kernel_launch(void* const* d_in, const int* in_sizes, int n_in,
                              void* d_out, int out_size) {
    const float* emb = (const float*)d_in[0];
    const int* labels = (const int*)d_in[1];
    float* out = (float*)d_out;

    cudaFuncSetAttribute(gram_tc_kernel,
                         cudaFuncAttributeMaxDynamicSharedMemorySize, SMEM_BYTES);

    normalize_kernel<<<NROWS / 16, 256>>>(emb);
    gram_tc_kernel<<<NTRI, 256, SMEM_BYTES>>>(labels);
    finalize_kernel<<<NFB, 256>>>(out);
}